// round 7
// baseline (speedup 1.0000x reference)
#include <cuda_runtime.h>

#define IMG      512
#define CROPPED  504
#define BATCH    16
#define TILE     32          // 32x32 output tile
#define IN_T     42          // TILE + 10 halo
#define IN_S     43          // odd stride for input tiles
#define VH       32
#define VSTRIDE  43          // odd stride for vv
#define NCHUNKS  6
#define CHUNK_A  6           // 6*6 = 36 >= 32 rows
#define NTX      16          // ceil(504/32)
#define NTY      16
#define TOTAL_CTAS (NTX * NTY * BATCH)   // 4096

__device__ double   g_acc;    // zero at module load; last CTA resets each call
__device__ unsigned g_count;

__global__ __launch_bounds__(256, 6) void ssim_main_kernel(
    const float* __restrict__ img1, const float* __restrict__ img2,
    float* __restrict__ out)
{
    __shared__ float  x1s[IN_T][IN_S];
    __shared__ float  x2s[IN_T][IN_S];
    // packed vertical 11-row running sums: {S1, S2, S11+S22, S12}
    __shared__ float4 vv[VH][VSTRIDE];

    const int b   = blockIdx.z;
    const int tj0 = blockIdx.x * TILE;
    const int ti0 = blockIdx.y * TILE;
    const int tid = threadIdx.x;

    const size_t base = (size_t)b * 3u * IMG * IMG;   // channel 0 of batch b

    // ===== Phase 0: cooperative halo load, gmem -> smem (high MLP) =========
    #pragma unroll
    for (int idx = tid; idx < IN_T * IN_T; idx += 256) {
        const int r = idx / IN_T;
        const int c = idx - r * IN_T;
        const int gi = ti0 + r - 5;
        const int gj = tj0 + c - 5;
        float a = 0.f, bb = 0.f;
        if ((unsigned)gi < (unsigned)CROPPED && (unsigned)gj < (unsigned)CROPPED) {
            const size_t off = base + (size_t)(gi + 4) * IMG + (size_t)(gj + 4);
            a  = __ldg(img1 + off);
            bb = __ldg(img2 + off);
        }
        x1s[r][c] = a;
        x2s[r][c] = bb;
    }
    __syncthreads();

    // ===== Phase A: vertical sliding sums, smem -> smem =====================
    // thread (c, chunk): column c, CHUNK_A-row chunk. Slides re-read smem
    // (29-cyc LDS, no register window, no LDG chain).
    if (tid < IN_T * NCHUNKS) {
        const int c     = tid % IN_T;
        const int chunk = tid / IN_T;
        const int r0    = chunk * CHUNK_A;

        float s1 = 0.f, s2 = 0.f, sA = 0.f, s12 = 0.f;
        #pragma unroll
        for (int k = 0; k < 11; k++) {
            const float a  = x1s[r0 + k][c];
            const float bb = x2s[r0 + k][c];
            s1  += a;
            s2  += bb;
            sA   = fmaf(a, a, fmaf(bb, bb, sA));
            s12  = fmaf(a, bb, s12);
        }
        if (r0 < VH) vv[r0][c] = make_float4(s1, s2, sA, s12);

        #pragma unroll
        for (int t = 1; t < CHUNK_A; t++) {
            const int r = r0 + t;
            if (r < VH) {
                const float an = x1s[r + 10][c];   // incoming input row
                const float bn = x2s[r + 10][c];
                const float ao = x1s[r - 1][c];    // outgoing input row
                const float bo = x2s[r - 1][c];
                s1  += an - ao;
                s2  += bn - bo;
                sA  += fmaf(an, an, bn * bn) - fmaf(ao, ao, bo * bo);
                s12 += an * bn - ao * bo;
                vv[r][c] = make_float4(s1, s2, sA, s12);
            }
        }
    }
    __syncthreads();

    // ===== Phase B: horizontal sliding + SSIM ===============================
    // i = tid&31 (row), seg = tid>>5 (0..7), 4 cols per thread.
    // LDS.128 octets: lanes 0-7 have consecutive i -> bank-group (3i+j) mod 8
    // distinct -> conflict-free.
    const float C1   = 6.5025f;                // (0.01*255)^2
    const float C2   = 58.5225f;               // (0.03*255)^2
    const float inv  = 1.0f / 121.0f;
    const float SCL  = 1.52587890625e-5f;      // 2^-16 pre-scale

    float local = 0.0f;
    {
        const int i  = tid & 31;
        const int j0 = (tid >> 5) * 4;

        if (ti0 + i < CROPPED) {
            float S1 = 0.f, S2 = 0.f, SA = 0.f, S12 = 0.f;
            #pragma unroll
            for (int k = 0; k < 11; k++) {
                const float4 t = vv[i][j0 + k];
                S1  += t.x;
                S2  += t.y;
                SA  += t.z;
                S12 += t.w;
            }

            float n[4], d[4];
            #pragma unroll
            for (int t = 0; t < 4; t++) {
                const int j = j0 + t;
                if (tj0 + j < CROPPED) {
                    const float mu1  = S1 * inv;
                    const float mu2  = S2 * inv;
                    const float m1s  = mu1 * mu1;
                    const float m2s  = mu2 * mu2;
                    const float m12  = mu1 * mu2;
                    const float sgA  = SA  * inv - m1s - m2s;  // sig1^2+sig2^2
                    const float sg12 = S12 * inv - m12;
                    const float num  = (2.0f * m12 + C1) * (2.0f * sg12 + C2);
                    const float den  = (m1s + m2s + C1) * (sgA + C2);
                    n[t] = num * SCL;
                    d[t] = den * SCL;
                } else {
                    n[t] = 0.0f;
                    d[t] = 1.0f;
                }
                if (t < 3) {   // slide: add col j+11, drop col j
                    const float4 va = vv[i][j + 11];
                    const float4 vs = vv[i][j];
                    S1  += va.x - vs.x;
                    S2  += va.y - vs.y;
                    SA  += va.z - vs.z;
                    S12 += va.w - vs.w;
                }
            }

            // 4-way ratio combine: one MUFU rcp per 4 pixels
            const float n12 = n[0] * d[1] + n[1] * d[0];
            const float d12 = d[0] * d[1];
            const float n34 = n[2] * d[3] + n[3] * d[2];
            const float d34 = d[2] * d[3];
            const float N   = n12 * d34 + n34 * d12;
            const float D   = d12 * d34;
            local += __fdividef(N, D);
        }
    }

    // ===== Block reduction -> one double atomic =============================
    #pragma unroll
    for (int o = 16; o > 0; o >>= 1)
        local += __shfl_down_sync(0xffffffffu, local, o);

    __shared__ float warpsum[8];
    if ((tid & 31) == 0) warpsum[tid >> 5] = local;
    __syncthreads();

    if (tid == 0) {
        float v = warpsum[0];
        #pragma unroll
        for (int w = 1; w < 8; w++) v += warpsum[w];
        atomicAdd(&g_acc, (double)v);

        // ---- last-CTA finalize ----
        __threadfence();
        const unsigned ticket = atomicAdd(&g_count, 1u);
        if (ticket == TOTAL_CTAS - 1) {
            const double acc = g_acc;
            out[0] = (float)(acc / ((double)BATCH * CROPPED * CROPPED));
            g_acc   = 0.0;   // reset for next graph replay
            g_count = 0u;
            __threadfence();
        }
    }
}

extern "C" void kernel_launch(void* const* d_in, const int* in_sizes, int n_in,
                              void* d_out, int out_size)
{
    const float* img1 = (const float*)d_in[0];
    const float* img2 = (const float*)d_in[1];
    float* out = (float*)d_out;

    dim3 grid(NTX, NTY, BATCH);
    ssim_main_kernel<<<grid, 256>>>(img1, img2, out);
}